// round 17
// baseline (speedup 1.0000x reference)
#include <cuda_runtime.h>
#include <cuda_bf16.h>
#include <cuda_fp16.h>
#include <cstdint>

#define Bn 16384
#define Tn 24
#define KZX 1056
#define INd 1060
#define G3  384
#define NC  512
#define WS  136

__device__ __align__(16) float g_sc[(size_t)Bn * NC];
__device__ __align__(16) __half g_wh[(size_t)512 * KZX];

__device__ __forceinline__ float sigf(float x){ return __fdividef(1.f, 1.f + __expf(-x)); }
__device__ __forceinline__ float tanha(float x){ return __fdividef(2.f, 1.f + __expf(-2.f*x)) - 1.f; }
__device__ __forceinline__ uint32_t s2u(const void* p){ uint32_t a; asm("{.reg .u64 t; cvta.to.shared.u64 t,%1; cvt.u32.u64 %0,t;}":"=r"(a):"l"(p)); return a; }
__device__ __forceinline__ uint32_t pkhf(float x, float y){ uint32_t d; asm("cvt.rn.f16x2.f32 %0,%1,%2;":"=r"(d):"f"(y),"f"(x)); return d; }
__device__ __forceinline__ float hlo(uint32_t v){ float f; asm("{.reg .b16 l,h; mov.b32 {l,h},%1; cvt.f32.f16 %0,l;}":"=f"(f):"r"(v)); return f; }
__device__ __forceinline__ float hhi(uint32_t v){ float f; asm("{.reg .b16 l,h; mov.b32 {l,h},%1; cvt.f32.f16 %0,h;}":"=f"(f):"r"(v)); return f; }
__device__ __forceinline__ void mmahf(float* c, const uint32_t* a, uint32_t b0, uint32_t b1){
    asm("mma.sync.aligned.m16n8k16.row.col.f32.f16.f16.f32 {%0,%1,%2,%3},{%4,%5,%6,%7},{%8,%9},{%0,%1,%2,%3};"
        : "+f"(c[0]),"+f"(c[1]),"+f"(c[2]),"+f"(c[3])
        : "r"(a[0]),"r"(a[1]),"r"(a[2]),"r"(a[3]),"r"(b0),"r"(b1));
}
__device__ __forceinline__ void ldsm4(uint32_t* r, uint32_t a){
    asm volatile("ldmatrix.sync.aligned.m8n8.x4.shared.b16 {%0,%1,%2,%3},[%4];"
        :"=r"(r[0]),"=r"(r[1]),"=r"(r[2]),"=r"(r[3]):"r"(a));
}

__global__ void convW(const float* __restrict__ W_ih, const float* __restrict__ W_dh){
    int i = blockIdx.x*256 + threadIdx.x;
    if(i >= 512*KZX) return;
    int row = i / KZX, k = i - row*KZX;
    float v = (row < G3) ? W_ih[(size_t)row*INd + k] : W_dh[(size_t)(row-G3)*KZX + k];
    g_wh[i] = __float2half(v);
}

// -------- Phase 1 (R16, known-good) --------
#define P1SM 52224
__global__ __launch_bounds__(512,1) void phase1f(
    const float* __restrict__ enc, const float* __restrict__ zin,
    const float* __restrict__ W_ih, const float* __restrict__ b_ih,
    const float* __restrict__ b_dh, const float* __restrict__ b_hh,
    const float* __restrict__ lobs, const float* __restrict__ sg)
{
    extern __shared__ __align__(1024) char sm[];
    uint32_t sb=s2u(sm);
    const uint32_t oAh=0, oAl=12288, oBh=24576;
    float* colb=(float*)(sm+49152); float* c58=(float*)(sm+50176); float* c59=(float*)(sm+51200);
    int tid=threadIdx.x, lane=tid&31, w=tid>>5;
    int wm=w>>3, wn=w&7;
    int m0=blockIdx.y*128, n0=blockIdx.x*256;

    if(tid<256){
        int j=n0+tid; float cb,w58=0.f,w59=0.f;
        if(j<G3){ cb=b_ih[j]+((j<256)?b_hh[j]:0.f);
                  w58=W_ih[(size_t)j*INd+1058]; w59=W_ih[(size_t)j*INd+1059]; }
        else cb=b_dh[j-G3];
        colb[tid]=cb; c58[tid]=w58; c59[tid]=w59;
    }
    int ra=tid>>2, kq=(tid&3)*4;
    int ma=m0+ra;
    const float* ae=enc+(size_t)ma*1024; const float* az=zin+(size_t)ma*32;
    const __half* bp0h=g_wh+(size_t)(n0+ra)*KZX;
    const __half* bp1h=bp0h+(size_t)128*KZX;

    float acc[4][4][4];
    #pragma unroll
    for(int i=0;i<4;i++)
        #pragma unroll
        for(int j2=0;j2<4;j2++){ acc[i][j2][0]=0.f; acc[i][j2][1]=0.f; acc[i][j2][2]=0.f; acc[i][j2][3]=0.f; }

#define LDT(kt) { int kk=(kt)*16+kq; \
    av=(kk<1024)?*(const float4*)(ae+kk):*(const float4*)(az+(kk-1024)); \
    bh0=*(const uint2*)(bp0h+kk); bh1=*(const uint2*)(bp1h+kk); }
#define STT(bf) { \
    uint32_t _off=(bf)*6144+ra*48+(tid&3)*8; \
    uint32_t _h0=pkhf(av.x,av.y), _h1=pkhf(av.z,av.w); \
    float _rx=av.x-hlo(_h0), _ry=av.y-hhi(_h0), _rz=av.z-hlo(_h1), _rw=av.w-hhi(_h1); \
    *(uint2*)(sm+oAh+_off)=make_uint2(_h0,_h1); \
    *(uint2*)(sm+oAl+_off)=make_uint2(pkhf(_rx,_ry),pkhf(_rz,_rw)); \
    *(uint2*)(sm+oBh+(bf)*12288+ra*48+(tid&3)*8)=bh0; \
    *(uint2*)(sm+oBh+(bf)*12288+(ra+128)*48+(tid&3)*8)=bh1; }

    float4 av; uint2 bh0,bh1;
    LDT(0); STT(0);
    __syncthreads();
    for(int kt=0;kt<66;kt++){
        int buf=kt&1;
        if(kt<65) LDT(kt+1);
        uint32_t aBh=sb+oAh+buf*6144+(uint32_t)((wm*64+(lane&15))*48+(lane>>4)*16);
        uint32_t aBl=aBh+(oAl-oAh);
        uint32_t bOff=(uint32_t)((wn*32+(lane>>4)*8+(lane&7))*48+((lane>>3)&1)*16);
        uint32_t bBh=sb+oBh+buf*12288+bOff;
        uint32_t Bh0[4],Bh1[4];
        ldsm4(Bh0,bBh); ldsm4(Bh1,bBh+16*48);
        #pragma unroll
        for(int mt=0;mt<4;mt++){
            uint32_t Af[4],Alf[4];
            ldsm4(Af, aBh+(uint32_t)(mt*16*48));
            ldsm4(Alf,aBl+(uint32_t)(mt*16*48));
            #pragma unroll
            for(int nt=0;nt<4;nt++){
                uint32_t b0=(nt<2?Bh0:Bh1)[(nt&1)*2], b1=(nt<2?Bh0:Bh1)[(nt&1)*2+1];
                mmahf(acc[mt][nt],Af,b0,b1);
                mmahf(acc[mt][nt],Alf,b0,b1);
            }
        }
        if(kt<65){ int nb=(kt+1)&1; STT(nb); }
        __syncthreads();
    }
    const float idt=1.f/4.8f;
    #pragma unroll
    for(int mt=0;mt<4;mt++){
        #pragma unroll
        for(int h=0;h<2;h++){
            int m=m0+wm*64+mt*16+(lane>>2)+8*h;
            float r0=(sg[2*m]-lobs[6*m])*idt, r1=(sg[2*m+1]-lobs[6*m+1])*idt;
            #pragma unroll
            for(int nt=0;nt<4;nt++){
                int jl=wn*32+nt*8+2*(lane&3);
                float vx=acc[mt][nt][2*h]  +colb[jl]  +r0*c58[jl]  +r1*c59[jl];
                float vy=acc[mt][nt][2*h+1]+colb[jl+1]+r0*c58[jl+1]+r1*c59[jl+1];
                *(float2*)&g_sc[(size_t)m*NC+n0+jl]=make_float2(vx,vy);
            }
        }
    }
#undef LDT
#undef STT
}

// -------- Phase 2: 32-row 4-warp groups (fp16 state) + 16-row tail pair --------
// smem: WHs @0 (104448), gis @104448 (86016), hx u32[112][68] @190464 (30464),
//       px f2[24][32] @220928 (6144), wash u32[384] @227072 (1536),
//       wmh u32[256] @228608 (1024), bhp u32[64] @229632 (256). total 229888.
#define SM2V 229888
__global__ __launch_bounds__(448,1) void phase2v(
    const float* __restrict__ W_hh, const float* __restrict__ W_ih,
    const float* __restrict__ b_hh,
    const float* __restrict__ W_mu, const float* __restrict__ b_mu,
    const float* __restrict__ W_std, const float* __restrict__ b_std,
    const float* __restrict__ lobs, const float* __restrict__ W_vel,
    const float* __restrict__ b_vel, const float* __restrict__ fut,
    float* __restrict__ out)
{
    extern __shared__ __align__(1024) char sm[];
    __half* WHs=(__half*)sm;
    uint32_t* gis=(uint32_t*)(sm+104448);
    uint32_t* hx=(uint32_t*)(sm+190464);
    float2* px=(float2*)(sm+220928);
    uint32_t* wash=(uint32_t*)(sm+227072);
    uint32_t* wmh=(uint32_t*)(sm+228608);
    uint32_t* bhp=(uint32_t*)(sm+229632);
    int tid=threadIdx.x, lane=tid&31, wid=tid>>5;
    int q=lane&3, rq=lane>>2;
    int rbb=blockIdx.x*112;

    for(int i=tid;i<G3*128;i+=448){
        int n=i>>7,k=i&127;
        WHs[n*WS+k]=__float2half(W_hh[i]);
    }
    for(int p=tid;p<112*192;p+=448){
        int row=p/192, j=p-row*192;
        if(rbb+row<Bn){
            float2 v=*(const float2*)&g_sc[(size_t)(rbb+row)*NC+2*j];
            gis[row*192+(j^((row&7)*4))]=pkhf(v.x,v.y);
        }
    }
    for(int i=tid;i<G3;i+=448)
        wash[i]=pkhf(W_ih[(size_t)i*INd+1056],W_ih[(size_t)i*INd+1057]);
    if(tid<128){ wmh[tid]=pkhf(W_mu[tid],W_mu[128+tid]);
                 wmh[128+tid]=pkhf(W_std[tid],W_std[128+tid]); }
    if(tid<64) bhp[tid]=pkhf(b_hh[256+2*tid],b_hh[257+2*tid]);
    __syncthreads();

    uint32_t sWH=s2u(WHs);
    uint32_t boff=(uint32_t)(((lane&7)*WS+(lane>>3)*8)*2);
    float bm0=b_mu[0],bm1=b_mu[1],bs0=b_std[0],bs1=b_std[1];

#define GATES_PKD(UR,UZ,UN,AR,HP0X,HP0Y,HP1X,HP1Y,UR1,UZ1,UN1,AR1,OUT0X,OUT0Y,OUT1X,OUT1Y) /* expanded inline below */

    if(wid<12){
        // ===== 32-row groups: 4 warps, 4-way N split, fp16 state =====
        int g=wid>>2, wsub=wid&3;
        int rbase=rbb+g*32;
        if(rbase>=Bn) return;
        uint32_t hbG=(uint32_t)(g*32*68);
        int rrel0n[2]={g*32+rq, g*32+16+rq};

        uint32_t Ah[2][8][4];
        #pragma unroll
        for(int nt=0;nt<2;nt++)
            #pragma unroll
            for(int kt=0;kt<8;kt++)
                #pragma unroll
                for(int rg=0;rg<4;rg++){
                    int r=rbase+nt*16+rq+((rg&1)?8:0);
                    int cb=kt*16+((rg>>1)*8)+2*q;
                    float2 v=*(const float2*)&g_sc[(size_t)r*NC+G3+cb];
                    Ah[nt][kt][rg]=pkhf(v.x,v.y);
                }
        float2 a0s0[2],a0s1[2];
        #pragma unroll
        for(int nt=0;nt<2;nt++){
            int r0=rbase+nt*16+rq, r1=r0+8;
            float s0=b_vel[0],s1=b_vel[1],u0=s0,u1=s1;
            #pragma unroll
            for(int k=0;k<6;k++){
                float v0=__ldg(&lobs[r0*6+k]), v1=__ldg(&lobs[r1*6+k]);
                s0=fmaf(v0,W_vel[k],s0); s1=fmaf(v0,W_vel[6+k],s1);
                u0=fmaf(v1,W_vel[k],u0); u1=fmaf(v1,W_vel[6+k],u1); }
            a0s0[nt]=make_float2(s0,s1); a0s1[nt]=make_float2(u0,u1);
        }

        for(int t=0;t<Tn;t++){
            float2 aR0[2],aR1[2];
            if(t==0){ aR0[0]=a0s0[0]; aR1[0]=a0s1[0]; aR0[1]=a0s0[1]; aR1[1]=a0s1[1]; }
            else {
                #pragma unroll
                for(int nt=0;nt<2;nt++){
                    int r0=rbase+nt*16+rq;
                    aR0[nt]=*(const float2*)&fut[((size_t)(t-1)*Bn+r0)*6+2];
                    aR1[nt]=*(const float2*)&fut[((size_t)(t-1)*Bn+r0+8)*6+2];
                }
            }
            float p8[2][8];
            #pragma unroll
            for(int nt=0;nt<2;nt++)
                #pragma unroll
                for(int i=0;i<8;i++) p8[nt][i]=0.f;

            #pragma unroll
            for(int c2=0;c2<4;c2++){
                int cg=wsub*4+c2;
                float cr[2][4],cz[2][4],cn[2][4];
                #pragma unroll
                for(int nt=0;nt<2;nt++)
                    #pragma unroll
                    for(int i=0;i<4;i++){ cr[nt][i]=0.f; cz[nt][i]=0.f; cn[nt][i]=0.f; }
                #pragma unroll
                for(int k2=0;k2<4;k2++){
                    uint32_t ab=(uint32_t)(((8*cg)*WS+k2*32)*2)+boff;
                    uint32_t br[4],bz[4],bn[4];
                    ldsm4(br, sWH+ab);
                    ldsm4(bz, sWH+ab+128*WS*2);
                    ldsm4(bn, sWH+ab+256*WS*2);
                    #pragma unroll
                    for(int h2=0;h2<2;h2++){
                        int kt=2*k2+h2;
                        #pragma unroll
                        for(int nt=0;nt<2;nt++){
                            mmahf(cr[nt],Ah[nt][kt],br[2*h2],br[2*h2+1]);
                            mmahf(cz[nt],Ah[nt][kt],bz[2*h2],bz[2*h2+1]);
                            mmahf(cn[nt],Ah[nt][kt],bn[2*h2],bn[2*h2+1]);
                        }
                    }
                }
                int jj=8*cg+2*q;
                uint32_t uwr0=wash[jj],     uwr1=wash[jj+1];
                uint32_t uwz0=wash[128+jj], uwz1=wash[128+jj+1];
                uint32_t uwn0=wash[256+jj], uwn1=wash[256+jj+1];
                uint32_t ubh=bhp[4*cg+q];
                uint32_t m0p=wmh[jj], m1p=wmh[jj+1], s0p=wmh[128+jj], s1p=wmh[128+jj+1];
                int jx=(cg*4+q)^(rq*4);
                int kth=cg>>1, co=(cg&1)*2;
                #pragma unroll
                for(int nt=0;nt<2;nt++){
                    int w0=rrel0n[nt]*192+jx, w1=w0+8*192;
                    uint32_t ur0=gis[w0], uz0=gis[w0+64], un0=gis[w0+128];
                    uint32_t ur1=gis[w1], uz1=gis[w1+64], un1=gis[w1+128];
                    float hp0x=hlo(Ah[nt][kth][co]),   hp0y=hhi(Ah[nt][kth][co]);
                    float hp1x=hlo(Ah[nt][kth][co+1]), hp1y=hhi(Ah[nt][kth][co+1]);
                    float r0x=sigf(hlo(ur0)+aR0[nt].x*hlo(uwr0)+aR0[nt].y*hhi(uwr0)+cr[nt][0]);
                    float r0y=sigf(hhi(ur0)+aR0[nt].x*hlo(uwr1)+aR0[nt].y*hhi(uwr1)+cr[nt][1]);
                    float r1x=sigf(hlo(ur1)+aR1[nt].x*hlo(uwr0)+aR1[nt].y*hhi(uwr0)+cr[nt][2]);
                    float r1y=sigf(hhi(ur1)+aR1[nt].x*hlo(uwr1)+aR1[nt].y*hhi(uwr1)+cr[nt][3]);
                    float z0x=sigf(hlo(uz0)+aR0[nt].x*hlo(uwz0)+aR0[nt].y*hhi(uwz0)+cz[nt][0]);
                    float z0y=sigf(hhi(uz0)+aR0[nt].x*hlo(uwz1)+aR0[nt].y*hhi(uwz1)+cz[nt][1]);
                    float z1x=sigf(hlo(uz1)+aR1[nt].x*hlo(uwz0)+aR1[nt].y*hhi(uwz0)+cz[nt][2]);
                    float z1y=sigf(hhi(uz1)+aR1[nt].x*hlo(uwz1)+aR1[nt].y*hhi(uwz1)+cz[nt][3]);
                    float n0x=tanha(hlo(un0)+aR0[nt].x*hlo(uwn0)+aR0[nt].y*hhi(uwn0)+r0x*(cn[nt][0]+hlo(ubh)));
                    float n0y=tanha(hhi(un0)+aR0[nt].x*hlo(uwn1)+aR0[nt].y*hhi(uwn1)+r0y*(cn[nt][1]+hhi(ubh)));
                    float n1x=tanha(hlo(un1)+aR1[nt].x*hlo(uwn0)+aR1[nt].y*hhi(uwn0)+r1x*(cn[nt][2]+hlo(ubh)));
                    float n1y=tanha(hhi(un1)+aR1[nt].x*hlo(uwn1)+aR1[nt].y*hhi(uwn1)+r1y*(cn[nt][3]+hhi(ubh)));
                    float h0x=(1.f-z0x)*n0x+z0x*hp0x;
                    float h0y=(1.f-z0y)*n0y+z0y*hp0y;
                    float h1x=(1.f-z1x)*n1x+z1x*hp1x;
                    float h1y=(1.f-z1y)*n1y+z1y*hp1y;
                    p8[nt][0]=fmaf(h0x,hlo(m0p),p8[nt][0]); p8[nt][0]=fmaf(h0y,hlo(m1p),p8[nt][0]);
                    p8[nt][1]=fmaf(h0x,hhi(m0p),p8[nt][1]); p8[nt][1]=fmaf(h0y,hhi(m1p),p8[nt][1]);
                    p8[nt][2]=fmaf(h0x,hlo(s0p),p8[nt][2]); p8[nt][2]=fmaf(h0y,hlo(s1p),p8[nt][2]);
                    p8[nt][3]=fmaf(h0x,hhi(s0p),p8[nt][3]); p8[nt][3]=fmaf(h0y,hhi(s1p),p8[nt][3]);
                    p8[nt][4]=fmaf(h1x,hlo(m0p),p8[nt][4]); p8[nt][4]=fmaf(h1y,hlo(m1p),p8[nt][4]);
                    p8[nt][5]=fmaf(h1x,hhi(m0p),p8[nt][5]); p8[nt][5]=fmaf(h1y,hhi(m1p),p8[nt][5]);
                    p8[nt][6]=fmaf(h1x,hlo(s0p),p8[nt][6]); p8[nt][6]=fmaf(h1y,hlo(s1p),p8[nt][6]);
                    p8[nt][7]=fmaf(h1x,hhi(s0p),p8[nt][7]); p8[nt][7]=fmaf(h1y,hhi(s1p),p8[nt][7]);
                    uint32_t wofs=hbG+(uint32_t)((nt*16+rq)*68+cg*4+q);
                    hx[wofs]     =pkhf(h0x,h0y);
                    hx[wofs+8*68]=pkhf(h1x,h1y);
                }
            }
            #pragma unroll
            for(int nt=0;nt<2;nt++){
                #pragma unroll
                for(int i=0;i<8;i++){
                    p8[nt][i]+=__shfl_xor_sync(~0u,p8[nt][i],1);
                    p8[nt][i]+=__shfl_xor_sync(~0u,p8[nt][i],2);
                }
                float2 mine;
                if(q<2) mine=make_float2((q&1)?p8[nt][4]:p8[nt][0],(q&1)?p8[nt][5]:p8[nt][1]);
                else    mine=make_float2((q&1)?p8[nt][6]:p8[nt][2],(q&1)?p8[nt][7]:p8[nt][3]);
                px[((g*2+nt)*4+wsub)*32+lane]=mine;
            }
            asm volatile("bar.sync %0,128;"::"r"(g+1):"memory");
            #pragma unroll
            for(int nt=0;nt<2;nt++)
                #pragma unroll
                for(int kt=0;kt<8;kt++)
                    #pragma unroll
                    for(int ch=0;ch<2;ch++){
                        uint32_t pw=hbG+(uint32_t)((2*kt+ch)*4+q);
                        Ah[nt][kt][ch*2  ]=hx[pw+(uint32_t)((nt*16+rq)*68)];
                        Ah[nt][kt][ch*2+1]=hx[pw+(uint32_t)((nt*16+rq+8)*68)];
                    }
            if(wsub==0){
                #pragma unroll
                for(int nt=0;nt<2;nt++){
                    int base=((g*2+nt)*4)*32+lane;
                    float2 s0=px[base], s1=px[base+32], s2=px[base+64], s3=px[base+96];
                    float vx=s0.x+s1.x+s2.x+s3.x, vy=s0.y+s1.y+s2.y+s3.y;
                    int orow=rbase+nt*16+rq+((q&1)?8:0);
                    if(q<2)
                        *(float2*)&out[(size_t)t*Bn*2+(size_t)orow*2]=make_float2(vx+bm0,vy+bm1);
                    else
                        *(float2*)&out[(size_t)(Tn+t)*Bn*2+(size_t)orow*2]=
                            make_float2(__expf(0.5f*(vx+bs0)),__expf(0.5f*(vy+bs1)));
                }
            }
            asm volatile("bar.sync %0,128;"::"r"(g+1):"memory");
        }
    } else {
        // ===== 16-row tail pair: 2 warps, 2-way split, fp16 state =====
        int half=wid&1;
        int rbase=rbb+96;
        if(rbase>=Bn) return;
        int row0=rbase+rq, row1=row0+8;
        uint32_t hb=(uint32_t)(96*68);
        int rrel0=96+rq;

        uint32_t Ah[8][4];
        #pragma unroll
        for(int kt=0;kt<8;kt++)
            #pragma unroll
            for(int rg=0;rg<4;rg++){
                int r=(rg&1)?row1:row0;
                int cb=kt*16+((rg>>1)*8)+2*q;
                float2 v=*(const float2*)&g_sc[(size_t)r*NC+G3+cb];
                Ah[kt][rg]=pkhf(v.x,v.y);
            }
        float2 a0r0,a0r1;
        { float s0=b_vel[0],s1=b_vel[1],t0=s0,t1=s1;
          #pragma unroll
          for(int k=0;k<6;k++){
              float v0=__ldg(&lobs[row0*6+k]), v1=__ldg(&lobs[row1*6+k]);
              s0=fmaf(v0,W_vel[k],s0); s1=fmaf(v0,W_vel[6+k],s1);
              t0=fmaf(v1,W_vel[k],t0); t1=fmaf(v1,W_vel[6+k],t1); }
          a0r0=make_float2(s0,s1); a0r1=make_float2(t0,t1); }

        for(int t=0;t<Tn;t++){
            float2 aR0,aR1;
            if(t==0){ aR0=a0r0; aR1=a0r1; }
            else { aR0=*(const float2*)&fut[((size_t)(t-1)*Bn+row0)*6+2];
                   aR1=*(const float2*)&fut[((size_t)(t-1)*Bn+row1)*6+2]; }
            float p0=0,p1=0,p2=0,p3=0,p4=0,p5=0,p6=0,p7=0;
            #pragma unroll
            for(int c2=0;c2<8;c2++){
                int cg=half*8+c2;
                float cr[4]={0,0,0,0}, cz[4]={0,0,0,0}, cn[4]={0,0,0,0};
                #pragma unroll
                for(int k2=0;k2<4;k2++){
                    uint32_t ab=(uint32_t)(((8*cg)*WS+k2*32)*2)+boff;
                    uint32_t br[4],bz[4],bn[4];
                    ldsm4(br, sWH+ab);
                    ldsm4(bz, sWH+ab+128*WS*2);
                    ldsm4(bn, sWH+ab+256*WS*2);
                    #pragma unroll
                    for(int h2=0;h2<2;h2++){
                        int kt=2*k2+h2;
                        mmahf(cr,Ah[kt],br[2*h2],br[2*h2+1]);
                        mmahf(cz,Ah[kt],bz[2*h2],bz[2*h2+1]);
                        mmahf(cn,Ah[kt],bn[2*h2],bn[2*h2+1]);
                    }
                }
                int jj=8*cg+2*q;
                uint32_t uwr0=wash[jj],     uwr1=wash[jj+1];
                uint32_t uwz0=wash[128+jj], uwz1=wash[128+jj+1];
                uint32_t uwn0=wash[256+jj], uwn1=wash[256+jj+1];
                uint32_t ubh=bhp[4*cg+q];
                uint32_t m0p=wmh[jj], m1p=wmh[jj+1], s0p=wmh[128+jj], s1p=wmh[128+jj+1];
                int jx=(cg*4+q)^(rq*4);
                int w0=rrel0*192+jx, w1=w0+8*192;
                uint32_t ur0=gis[w0], uz0=gis[w0+64], un0=gis[w0+128];
                uint32_t ur1=gis[w1], uz1=gis[w1+64], un1=gis[w1+128];
                int kth=cg>>1, co=(cg&1)*2;
                float hp0x=hlo(Ah[kth][co]),   hp0y=hhi(Ah[kth][co]);
                float hp1x=hlo(Ah[kth][co+1]), hp1y=hhi(Ah[kth][co+1]);
                float r0x=sigf(hlo(ur0)+aR0.x*hlo(uwr0)+aR0.y*hhi(uwr0)+cr[0]);
                float r0y=sigf(hhi(ur0)+aR0.x*hlo(uwr1)+aR0.y*hhi(uwr1)+cr[1]);
                float r1x=sigf(hlo(ur1)+aR1.x*hlo(uwr0)+aR1.y*hhi(uwr0)+cr[2]);
                float r1y=sigf(hhi(ur1)+aR1.x*hlo(uwr1)+aR1.y*hhi(uwr1)+cr[3]);
                float z0x=sigf(hlo(uz0)+aR0.x*hlo(uwz0)+aR0.y*hhi(uwz0)+cz[0]);
                float z0y=sigf(hhi(uz0)+aR0.x*hlo(uwz1)+aR0.y*hhi(uwz1)+cz[1]);
                float z1x=sigf(hlo(uz1)+aR1.x*hlo(uwz0)+aR1.y*hhi(uwz0)+cz[2]);
                float z1y=sigf(hhi(uz1)+aR1.x*hlo(uwz1)+aR1.y*hhi(uwz1)+cz[3]);
                float n0x=tanha(hlo(un0)+aR0.x*hlo(uwn0)+aR0.y*hhi(uwn0)+r0x*(cn[0]+hlo(ubh)));
                float n0y=tanha(hhi(un0)+aR0.x*hlo(uwn1)+aR0.y*hhi(uwn1)+r0y*(cn[1]+hhi(ubh)));
                float n1x=tanha(hlo(un1)+aR1.x*hlo(uwn0)+aR1.y*hhi(uwn0)+r1x*(cn[2]+hlo(ubh)));
                float n1y=tanha(hhi(un1)+aR1.x*hlo(uwn1)+aR1.y*hhi(uwn1)+r1y*(cn[3]+hhi(ubh)));
                float h0x=(1.f-z0x)*n0x+z0x*hp0x;
                float h0y=(1.f-z0y)*n0y+z0y*hp0y;
                float h1x=(1.f-z1x)*n1x+z1x*hp1x;
                float h1y=(1.f-z1y)*n1y+z1y*hp1y;
                p0=fmaf(h0x,hlo(m0p),p0); p0=fmaf(h0y,hlo(m1p),p0);
                p1=fmaf(h0x,hhi(m0p),p1); p1=fmaf(h0y,hhi(m1p),p1);
                p2=fmaf(h0x,hlo(s0p),p2); p2=fmaf(h0y,hlo(s1p),p2);
                p3=fmaf(h0x,hhi(s0p),p3); p3=fmaf(h0y,hhi(s1p),p3);
                p4=fmaf(h1x,hlo(m0p),p4); p4=fmaf(h1y,hlo(m1p),p4);
                p5=fmaf(h1x,hhi(m0p),p5); p5=fmaf(h1y,hhi(m1p),p5);
                p6=fmaf(h1x,hlo(s0p),p6); p6=fmaf(h1y,hlo(s1p),p6);
                p7=fmaf(h1x,hhi(s0p),p7); p7=fmaf(h1y,hhi(s1p),p7);
                uint32_t wofs=hb+(uint32_t)(rq*68+cg*4+q);
                hx[wofs]     =pkhf(h0x,h0y);
                hx[wofs+8*68]=pkhf(h1x,h1y);
            }
            p0+=__shfl_xor_sync(~0u,p0,1); p0+=__shfl_xor_sync(~0u,p0,2);
            p1+=__shfl_xor_sync(~0u,p1,1); p1+=__shfl_xor_sync(~0u,p1,2);
            p2+=__shfl_xor_sync(~0u,p2,1); p2+=__shfl_xor_sync(~0u,p2,2);
            p3+=__shfl_xor_sync(~0u,p3,1); p3+=__shfl_xor_sync(~0u,p3,2);
            p4+=__shfl_xor_sync(~0u,p4,1); p4+=__shfl_xor_sync(~0u,p4,2);
            p5+=__shfl_xor_sync(~0u,p5,1); p5+=__shfl_xor_sync(~0u,p5,2);
            p6+=__shfl_xor_sync(~0u,p6,1); p6+=__shfl_xor_sync(~0u,p6,2);
            p7+=__shfl_xor_sync(~0u,p7,1); p7+=__shfl_xor_sync(~0u,p7,2);
            float2 mine;
            if(q<2) mine=make_float2((q&1)?p4:p0,(q&1)?p5:p1);
            else    mine=make_float2((q&1)?p6:p2,(q&1)?p7:p3);
            *(float2*)&hx[(uint32_t)((half*32+lane)*68+64)]=mine;
            asm volatile("bar.sync 5,64;":::"memory");
            #pragma unroll
            for(int kt=0;kt<8;kt++)
                #pragma unroll
                for(int ch=0;ch<2;ch++){
                    uint32_t pw=hb+(uint32_t)((2*kt+ch)*4+q);
                    Ah[kt][ch*2  ]=hx[pw+rq*68];
                    Ah[kt][ch*2+1]=hx[pw+(rq+8)*68];
                }
            if(half==0){
                float2 other=*(const float2*)&hx[(uint32_t)((32+lane)*68+64)];
                float vx=mine.x+other.x, vy=mine.y+other.y;
                int orow=(q&1)?row1:row0;
                if(q<2)
                    *(float2*)&out[(size_t)t*Bn*2+(size_t)orow*2]=make_float2(vx+bm0,vy+bm1);
                else
                    *(float2*)&out[(size_t)(Tn+t)*Bn*2+(size_t)orow*2]=
                        make_float2(__expf(0.5f*(vx+bs0)),__expf(0.5f*(vy+bs1)));
            }
            asm volatile("bar.sync 5,64;":::"memory");
        }
    }
}

extern "C" void kernel_launch(void* const* d_in, const int* in_sizes, int n_in,
                              void* d_out, int out_size) {
    const float* lobs=(const float*)d_in[0];
    const float* enc =(const float*)d_in[1];
    const float* zin =(const float*)d_in[2];
    const float* sg  =(const float*)d_in[3];
    const float* fut =(const float*)d_in[4];
    const float* W_dh=(const float*)d_in[5];
    const float* b_dh=(const float*)d_in[6];
    const float* W_vel=(const float*)d_in[7];
    const float* b_vel=(const float*)d_in[8];
    const float* W_ih=(const float*)d_in[9];
    const float* b_ih=(const float*)d_in[10];
    const float* W_hh=(const float*)d_in[11];
    const float* b_hh=(const float*)d_in[12];
    const float* W_mu=(const float*)d_in[13];
    const float* b_mu=(const float*)d_in[14];
    const float* W_std=(const float*)d_in[15];
    const float* b_std=(const float*)d_in[16];
    float* out=(float*)d_out;

    convW<<<(512*KZX+255)/256,256>>>(W_ih,W_dh);

    cudaFuncSetAttribute(phase1f, cudaFuncAttributeMaxDynamicSharedMemorySize, P1SM);
    phase1f<<<dim3(2,128),512,P1SM>>>(enc,zin,W_ih,b_ih,b_dh,b_hh,lobs,sg);

    cudaFuncSetAttribute(phase2v, cudaFuncAttributeMaxDynamicSharedMemorySize, SM2V);
    phase2v<<<147,448,SM2V>>>(W_hh,W_ih,b_hh,W_mu,b_mu,W_std,b_std,
                              lobs,W_vel,b_vel,fut,out);
}